// round 4
// baseline (speedup 1.0000x reference)
#include <cuda_runtime.h>
#include <cuda_bf16.h>
#include <cstdint>
#include <cstddef>

#define DI __device__ __forceinline__

// ---------------------------------------------------------------------------
// Problem constants
// ---------------------------------------------------------------------------
static constexpr int BATCH = 4;
static constexpr int DIM   = 4096;
static constexpr int KB    = 128;            // 4096/32 scale blocks per vector

// GEMM tiling
static constexpr int BM = 128, BN = 128, BK = 64;
static constexpr int STAGES  = 4;
static constexpr int KTILES  = DIM / BK;      // 64
static constexpr int A_STAGE = BM * BK * 2;   // 16384 B
static constexpr int STAGE_B = 2 * A_STAGE;   // 32768 B (A + B)
static constexpr unsigned SMEM_TOTAL = STAGES * STAGE_B;   // 131072

// ---------------------------------------------------------------------------
// Scratch (device globals; no cudaMalloc allowed)
// ---------------------------------------------------------------------------
__device__ __align__(16) __nv_bfloat16 g_Adq[(size_t)BATCH * DIM * DIM]; // [b][m][k]
__device__ __align__(16) __nv_bfloat16 g_Bdq[(size_t)BATCH * DIM * DIM]; // [b][n][k]

// ---------------------------------------------------------------------------
// Helpers
// ---------------------------------------------------------------------------
DI uint32_t smem_u32(const void* p) {
    uint32_t a;
    asm("{ .reg .u64 t; cvta.to.shared.u64 t, %1; cvt.u32.u64 %0, t; }" : "=r"(a) : "l"(p));
    return a;
}

DI void cp_async16(uint32_t dst, const void* src) {
    asm volatile("cp.async.cg.shared.global [%0], [%1], 16;" :: "r"(dst), "l"(src) : "memory");
}
DI void cp_commit() { asm volatile("cp.async.commit_group;" ::: "memory"); }
template <int N> DI void cp_wait() { asm volatile("cp.async.wait_group %0;" :: "n"(N) : "memory"); }

DI void ldmatrix_x4(uint32_t& r0, uint32_t& r1, uint32_t& r2, uint32_t& r3, uint32_t addr) {
    asm volatile("ldmatrix.sync.aligned.m8n8.x4.shared.b16 {%0,%1,%2,%3}, [%4];"
                 : "=r"(r0), "=r"(r1), "=r"(r2), "=r"(r3) : "r"(addr));
}

DI void mma_bf16(float& c0, float& c1, float& c2, float& c3,
                 uint32_t a0, uint32_t a1, uint32_t a2, uint32_t a3,
                 uint32_t b0, uint32_t b1) {
    asm volatile(
        "mma.sync.aligned.m16n8k16.row.col.f32.bf16.bf16.f32 "
        "{%0,%1,%2,%3}, {%4,%5,%6,%7}, {%8,%9}, {%0,%1,%2,%3};"
        : "+f"(c0), "+f"(c1), "+f"(c2), "+f"(c3)
        : "r"(a0), "r"(a1), "r"(a2), "r"(a3), "r"(b0), "r"(b1));
}

DI uint32_t pack_bf16x2(float lo, float hi) {
    uint32_t r;
    asm("cvt.rn.bf16x2.f32 %0, %1, %2;" : "=r"(r) : "f"(hi), "f"(lo));
    return r;
}

DI uint32_t swz(uint32_t off) { return off ^ ((off >> 3) & 0x70); }   // SW128, 128B rows

// ---------------------------------------------------------------------------
// MX fake-quantization: 32 values -> dequantized bf16 (exact, matches reference)
// ---------------------------------------------------------------------------
DI void dequant_block32(const float* x, uint32_t* w /*16 packed bf16x2*/) {
    float amax = 0.0f;
#pragma unroll
    for (int i = 0; i < 32; ++i) amax = fmaxf(amax, fabsf(x[i]));

    float inv, scale;
    if (amax > 0.0f) {
        int eb = (int)(__float_as_uint(amax) >> 23) & 0xFF;  // floor(log2)+127 (amax normal)
        int sb = eb - 2;                                      // exponent bits of 2^(shexp-2)
        if (sb < 1) sb = 1;
        scale = __uint_as_float((uint32_t)sb << 23);          // exact power of 2
        inv   = __uint_as_float((uint32_t)(254 - sb) << 23);  // exact reciprocal
    } else {
        scale = 1.0f; inv = 1.0f;
    }

    float r[32];
#pragma unroll
    for (int i = 0; i < 32; ++i) {
        float v = x[i] * inv;                 // exact (power-of-2)
        float a = fminf(fabsf(v), 6.0f);
        float q;
        if (a < 2.0f)      q = rintf(a * 2.0f) * 0.5f;   // step .5, RNE (matches jnp.round)
        else if (a < 4.0f) q = rintf(a);                 // step 1
        else               q = rintf(a * 0.5f) * 2.0f;   // step 2
        q = (v < 0.0f) ? -q : q;
        r[i] = q * scale;                     // exact; bf16-exact value
    }
#pragma unroll
    for (int i = 0; i < 16; ++i) w[i] = pack_bf16x2(r[2 * i], r[2 * i + 1]);
}

// A: [b][m][k] fp32, quantize along k (contiguous). One thread per 32-block.
__global__ void __launch_bounds__(256) quantA_kernel(const float* __restrict__ A) {
    size_t idx = (size_t)blockIdx.x * 256 + threadIdx.x;   // (b*4096+m)*128 + kb
    const float4* src = (const float4*)(A + idx * 32);
    float x[32];
#pragma unroll
    for (int i = 0; i < 8; ++i) {
        float4 v = src[i];
        x[i*4+0] = v.x; x[i*4+1] = v.y; x[i*4+2] = v.z; x[i*4+3] = v.w;
    }
    uint32_t w[16];
    dequant_block32(x, w);
    uint4* dst = (uint4*)(g_Adq + idx * 32);
#pragma unroll
    for (int i = 0; i < 4; ++i)
        dst[i] = make_uint4(w[i*4+0], w[i*4+1], w[i*4+2], w[i*4+3]);
}

// B: [b][k][n] fp32, quantize along k (stride DIM). Output transposed: [b][n][k].
__global__ void __launch_bounds__(256) quantB_kernel(const float* __restrict__ B) {
    int n  = blockIdx.x * 256 + threadIdx.x;
    int kb = blockIdx.y;
    int b  = blockIdx.z;
    const float* src = B + ((size_t)b << 24) + (size_t)kb * 32 * DIM + n;
    float x[32];
#pragma unroll
    for (int r = 0; r < 32; ++r) x[r] = src[(size_t)r * DIM];
    uint32_t w[16];
    dequant_block32(x, w);
    uint4* dst = (uint4*)(g_Bdq + ((size_t)b << 24) + (size_t)n * DIM + kb * 32);
#pragma unroll
    for (int i = 0; i < 4; ++i)
        dst[i] = make_uint4(w[i*4+0], w[i*4+1], w[i*4+2], w[i*4+3]);
}

// ---------------------------------------------------------------------------
// GEMM: 128x128 CTA tile, bf16 mma.sync m16n8k16, 4-stage cp.async pipeline
// 8 warps in 4x2 grid; warp tile 32(M) x 64(N).
// ---------------------------------------------------------------------------
DI void load_stage(uint32_t sb_, int stage, const __nv_bfloat16* Ab,
                   const __nv_bfloat16* Bb, int kt, int tid) {
    uint32_t sA = sb_ + stage * STAGE_B;
    uint32_t sB = sA + A_STAGE;
    const char* Ag = (const char*)Ab + (size_t)kt * (BK * 2);
    const char* Bg = (const char*)Bb + (size_t)kt * (BK * 2);
#pragma unroll
    for (int t = 0; t < 4; ++t) {
        int c   = tid + t * 256;            // 0..1023 16B-chunks
        int row = c >> 3;
        int cc  = (c & 7) * 16;             // byte within 128B row
        uint32_t sw = swz((uint32_t)(row * 128 + cc));
        size_t g = (size_t)row * (DIM * 2) + cc;
        cp_async16(sA + sw, Ag + g);
        cp_async16(sB + sw, Bg + g);
    }
}

__global__ void __launch_bounds__(256, 1)
gemm_kernel(float* __restrict__ out) {
    extern __shared__ char smem[];
    uint32_t sb_ = smem_u32(smem);
    int tid = threadIdx.x, warp = tid >> 5, lane = tid & 31;
    int wm = warp >> 1, wn = warp & 1;
    int tn = blockIdx.x, tm = blockIdx.y, b = blockIdx.z;

    const __nv_bfloat16* Abase = g_Adq + ((size_t)b << 24) + (size_t)tm * BM * DIM;
    const __nv_bfloat16* Bbase = g_Bdq + ((size_t)b << 24) + (size_t)tn * BN * DIM;

    float c[2][8][4];
#pragma unroll
    for (int i = 0; i < 2; ++i)
#pragma unroll
        for (int j = 0; j < 8; ++j)
#pragma unroll
            for (int q = 0; q < 4; ++q) c[i][j][q] = 0.0f;

    // prologue: prefetch 3 stages
#pragma unroll
    for (int p = 0; p < STAGES - 1; ++p) {
        load_stage(sb_, p, Abase, Bbase, p, tid);
        cp_commit();
    }

    // precomputed ldmatrix smem offsets (within a stage) for kstep 0
    // A: matrices rows (lane&15), col-block (lane>>4)*8
    uint32_t a_off[2];
#pragma unroll
    for (int mt = 0; mt < 2; ++mt) {
        int r = wm * 32 + mt * 16 + (lane & 15);
        int cbyte = ((lane >> 4) * 8) * 2;
        a_off[mt] = swz((uint32_t)(r * 128 + cbyte));
    }
    // B: matrix idx m=lane>>3: row n0+(m>>1)*8+(lane&7), col (m&1)*8
    uint32_t b_off[4];
#pragma unroll
    for (int p = 0; p < 4; ++p) {
        int m = lane >> 3;
        int r = wn * 64 + p * 16 + ((m >> 1) * 8) + (lane & 7);
        int cbyte = ((m & 1) * 8) * 2;
        b_off[p] = swz((uint32_t)(r * 128 + cbyte));
    }

    for (int i = 0; i < KTILES; ++i) {
        cp_wait<STAGES - 2>();
        __syncthreads();
        int pf = i + STAGES - 1;
        if (pf < KTILES) {
            load_stage(sb_, pf & (STAGES - 1), Abase, Bbase, pf, tid);
        }
        cp_commit();   // commit (possibly empty) group to keep wait counts uniform

        uint32_t stA = sb_ + (i & (STAGES - 1)) * STAGE_B;
        uint32_t stB = stA + A_STAGE;
#pragma unroll
        for (int ks = 0; ks < 4; ++ks) {
            uint32_t kbyte = (uint32_t)(ks * 16 * 2);
            // swizzle of +kbyte within row: byte-XOR pattern — recompute via swz on the fly
            uint32_t af[2][4];
#pragma unroll
            for (int mt = 0; mt < 2; ++mt) {
                // base row offset without swizzle, add kstep bytes, then swizzle
                int r = wm * 32 + mt * 16 + (lane & 15);
                int cbyte = ((lane >> 4) * 8) * 2 + kbyte;
                uint32_t ad = stA + swz((uint32_t)(r * 128 + cbyte));
                ldmatrix_x4(af[mt][0], af[mt][1], af[mt][2], af[mt][3], ad);
            }
            uint32_t bf[8][2];
#pragma unroll
            for (int p = 0; p < 4; ++p) {
                int m = lane >> 3;
                int r = wn * 64 + p * 16 + ((m >> 1) * 8) + (lane & 7);
                int cbyte = ((m & 1) * 8) * 2 + kbyte;
                uint32_t bd = stB + swz((uint32_t)(r * 128 + cbyte));
                uint32_t r0, r1, r2, r3;
                ldmatrix_x4(r0, r1, r2, r3, bd);
                bf[p*2+0][0] = r0; bf[p*2+0][1] = r1;
                bf[p*2+1][0] = r2; bf[p*2+1][1] = r3;
            }
#pragma unroll
            for (int mt = 0; mt < 2; ++mt)
#pragma unroll
                for (int nt = 0; nt < 8; ++nt)
                    mma_bf16(c[mt][nt][0], c[mt][nt][1], c[mt][nt][2], c[mt][nt][3],
                             af[mt][0], af[mt][1], af[mt][2], af[mt][3],
                             bf[nt][0], bf[nt][1]);
        }
        __syncthreads();
    }

    // epilogue: direct global stores (float2 per reg pair)
    int g = lane >> 2, t4 = lane & 3;
    float* obase = out + ((size_t)b << 24)
                 + (size_t)(tm * BM + wm * 32) * DIM + tn * BN + wn * 64;
#pragma unroll
    for (int mt = 0; mt < 2; ++mt) {
#pragma unroll
        for (int nt = 0; nt < 8; ++nt) {
            int colb = nt * 8 + t4 * 2;
            float* p0 = obase + (size_t)(mt * 16 + g) * DIM + colb;
            *(float2*)p0 = make_float2(c[mt][nt][0], c[mt][nt][1]);
            float* p1 = obase + (size_t)(mt * 16 + g + 8) * DIM + colb;
            *(float2*)p1 = make_float2(c[mt][nt][2], c[mt][nt][3]);
        }
    }
}

// ---------------------------------------------------------------------------
extern "C" void kernel_launch(void* const* d_in, const int* in_sizes, int n_in,
                              void* d_out, int out_size) {
    const float* A = (const float*)d_in[0];
    const float* B = (const float*)d_in[1];
    float* out = (float*)d_out;

    quantA_kernel<<<(BATCH * DIM * KB) / 256, 256>>>(A);
    quantB_kernel<<<dim3(DIM / 256, KB, BATCH), 256>>>(B);

    cudaFuncSetAttribute(gemm_kernel, cudaFuncAttributeMaxDynamicSharedMemorySize, SMEM_TOTAL);
    gemm_kernel<<<dim3(DIM / BN, DIM / BM, BATCH), 256, SMEM_TOTAL>>>(out);
}

// round 5
// speedup vs baseline: 1.1424x; 1.1424x over previous
#include <cuda_runtime.h>
#include <cuda_bf16.h>
#include <cstdint>
#include <cstddef>

#define DI __device__ __forceinline__

// ---------------------------------------------------------------------------
// Problem constants
// ---------------------------------------------------------------------------
static constexpr int BATCH = 4;
static constexpr int DIM   = 4096;
static constexpr int KB    = 128;            // 4096/32 scale blocks per vector

// GEMM tiling
static constexpr int BM = 128, BN = 256, BK = 64;
static constexpr int NTHREADS = 512;          // 16 warps, 4x4
static constexpr int STAGES  = 3;
static constexpr int KTILES  = DIM / BK;      // 64
static constexpr int A_STAGE = BM * BK * 2;   // 16384 B
static constexpr int B_STAGE = BN * BK * 2;   // 32768 B
static constexpr int STAGE_B = A_STAGE + B_STAGE;            // 49152
static constexpr unsigned SMEM_TOTAL = STAGES * STAGE_B;     // 147456

// ---------------------------------------------------------------------------
// Scratch (device globals; no cudaMalloc allowed)
// ---------------------------------------------------------------------------
__device__ __align__(16) __nv_bfloat16 g_Adq[(size_t)BATCH * DIM * DIM]; // [b][m][k]
__device__ __align__(16) __nv_bfloat16 g_Bdq[(size_t)BATCH * DIM * DIM]; // [b][n][k]

// ---------------------------------------------------------------------------
// Helpers
// ---------------------------------------------------------------------------
DI uint32_t smem_u32(const void* p) {
    uint32_t a;
    asm("{ .reg .u64 t; cvta.to.shared.u64 t, %1; cvt.u32.u64 %0, t; }" : "=r"(a) : "l"(p));
    return a;
}

DI void cp_async16(uint32_t dst, const void* src) {
    asm volatile("cp.async.cg.shared.global [%0], [%1], 16;" :: "r"(dst), "l"(src) : "memory");
}
DI void cp_commit() { asm volatile("cp.async.commit_group;" ::: "memory"); }
template <int N> DI void cp_wait() { asm volatile("cp.async.wait_group %0;" :: "n"(N) : "memory"); }

DI void ldmatrix_x4(uint32_t& r0, uint32_t& r1, uint32_t& r2, uint32_t& r3, uint32_t addr) {
    asm volatile("ldmatrix.sync.aligned.m8n8.x4.shared.b16 {%0,%1,%2,%3}, [%4];"
                 : "=r"(r0), "=r"(r1), "=r"(r2), "=r"(r3) : "r"(addr));
}

DI void mma_bf16(float& c0, float& c1, float& c2, float& c3,
                 uint32_t a0, uint32_t a1, uint32_t a2, uint32_t a3,
                 uint32_t b0, uint32_t b1) {
    asm volatile(
        "mma.sync.aligned.m16n8k16.row.col.f32.bf16.bf16.f32 "
        "{%0,%1,%2,%3}, {%4,%5,%6,%7}, {%8,%9}, {%0,%1,%2,%3};"
        : "+f"(c0), "+f"(c1), "+f"(c2), "+f"(c3)
        : "r"(a0), "r"(a1), "r"(a2), "r"(a3), "r"(b0), "r"(b1));
}

DI uint32_t pack_bf16x2(float lo, float hi) {
    uint32_t r;
    asm("cvt.rn.bf16x2.f32 %0, %1, %2;" : "=r"(r) : "f"(hi), "f"(lo));
    return r;
}

DI uint32_t swz(uint32_t off) { return off ^ ((off >> 3) & 0x70); }   // SW128, 128B rows

// ---------------------------------------------------------------------------
// MX fake-quantization: 32 values -> dequantized bf16 (exact, matches reference)
// ---------------------------------------------------------------------------
DI void dequant_block32(const float* x, uint32_t* w /*16 packed bf16x2*/) {
    float amax = 0.0f;
#pragma unroll
    for (int i = 0; i < 32; ++i) amax = fmaxf(amax, fabsf(x[i]));

    float inv, scale;
    if (amax > 0.0f) {
        int eb = (int)(__float_as_uint(amax) >> 23) & 0xFF;  // floor(log2)+127
        int sb = eb - 2;                                      // exponent of 2^(shexp-2)
        if (sb < 1) sb = 1;
        scale = __uint_as_float((uint32_t)sb << 23);          // exact power of 2
        inv   = __uint_as_float((uint32_t)(254 - sb) << 23);  // exact reciprocal
    } else {
        scale = 1.0f; inv = 1.0f;
    }

    float r[32];
#pragma unroll
    for (int i = 0; i < 32; ++i) {
        float v = x[i] * inv;                 // exact (power-of-2)
        float a = fminf(fabsf(v), 6.0f);
        float q;
        if (a < 2.0f)      q = rintf(a * 2.0f) * 0.5f;   // step .5, RNE
        else if (a < 4.0f) q = rintf(a);                 // step 1
        else               q = rintf(a * 0.5f) * 2.0f;   // step 2
        q = (v < 0.0f) ? -q : q;
        r[i] = q * scale;                     // exact; bf16-exact value
    }
#pragma unroll
    for (int i = 0; i < 16; ++i) w[i] = pack_bf16x2(r[2 * i], r[2 * i + 1]);
}

// A: [b][m][k] fp32, quantize along k (contiguous). One thread per 32-block.
__global__ void __launch_bounds__(256) quantA_kernel(const float* __restrict__ A) {
    size_t idx = (size_t)blockIdx.x * 256 + threadIdx.x;
    const float4* src = (const float4*)(A + idx * 32);
    float x[32];
#pragma unroll
    for (int i = 0; i < 8; ++i) {
        float4 v = src[i];
        x[i*4+0] = v.x; x[i*4+1] = v.y; x[i*4+2] = v.z; x[i*4+3] = v.w;
    }
    uint32_t w[16];
    dequant_block32(x, w);
    uint4* dst = (uint4*)(g_Adq + idx * 32);
#pragma unroll
    for (int i = 0; i < 4; ++i)
        dst[i] = make_uint4(w[i*4+0], w[i*4+1], w[i*4+2], w[i*4+3]);
}

// B: [b][k][n] fp32, quantize along k (stride DIM). Output transposed: [b][n][k].
__global__ void __launch_bounds__(256) quantB_kernel(const float* __restrict__ B) {
    int n  = blockIdx.x * 256 + threadIdx.x;
    int kb = blockIdx.y;
    int b  = blockIdx.z;
    const float* src = B + ((size_t)b << 24) + (size_t)kb * 32 * DIM + n;
    float x[32];
#pragma unroll
    for (int r = 0; r < 32; ++r) x[r] = src[(size_t)r * DIM];
    uint32_t w[16];
    dequant_block32(x, w);
    uint4* dst = (uint4*)(g_Bdq + ((size_t)b << 24) + (size_t)n * DIM + kb * 32);
#pragma unroll
    for (int i = 0; i < 4; ++i)
        dst[i] = make_uint4(w[i*4+0], w[i*4+1], w[i*4+2], w[i*4+3]);
}

// ---------------------------------------------------------------------------
// GEMM: 128x256 CTA tile, bf16 mma.sync m16n8k16, 3-stage cp.async pipeline
// 16 warps in 4x4 grid; warp tile 32(M) x 64(N).
// ---------------------------------------------------------------------------
DI void load_stage(uint32_t sb_, int stage, const __nv_bfloat16* Ab,
                   const __nv_bfloat16* Bb, int kt, int tid) {
    uint32_t sA = sb_ + stage * STAGE_B;
    uint32_t sB = sA + A_STAGE;
    const char* Ag = (const char*)Ab + (size_t)kt * (BK * 2);
    const char* Bg = (const char*)Bb + (size_t)kt * (BK * 2);
    // A: 1024 16B-chunks (128 rows x 8)
#pragma unroll
    for (int t = 0; t < 2; ++t) {
        int c   = tid + t * NTHREADS;
        int row = c >> 3;
        int cc  = (c & 7) * 16;
        cp_async16(sA + swz((uint32_t)(row * 128 + cc)),
                   Ag + (size_t)row * (DIM * 2) + cc);
    }
    // B: 2048 16B-chunks (256 rows x 8)
#pragma unroll
    for (int t = 0; t < 4; ++t) {
        int c   = tid + t * NTHREADS;
        int row = c >> 3;
        int cc  = (c & 7) * 16;
        cp_async16(sB + swz((uint32_t)(row * 128 + cc)),
                   Bg + (size_t)row * (DIM * 2) + cc);
    }
}

__global__ void __launch_bounds__(NTHREADS, 1)
gemm_kernel(float* __restrict__ out) {
    extern __shared__ char smem[];
    uint32_t sb_ = smem_u32(smem);
    int tid = threadIdx.x, warp = tid >> 5, lane = tid & 31;
    int wm = warp >> 2, wn = warp & 3;        // 4x4 warp grid
    int tn = blockIdx.x, tm = blockIdx.y, b = blockIdx.z;

    const __nv_bfloat16* Abase = g_Adq + ((size_t)b << 24) + (size_t)tm * BM * DIM;
    const __nv_bfloat16* Bbase = g_Bdq + ((size_t)b << 24) + (size_t)tn * BN * DIM;

    float c[2][8][4];
#pragma unroll
    for (int i = 0; i < 2; ++i)
#pragma unroll
        for (int j = 0; j < 8; ++j)
#pragma unroll
            for (int q = 0; q < 4; ++q) c[i][j][q] = 0.0f;

    // prologue: prefetch STAGES-1 stages
#pragma unroll
    for (int p = 0; p < STAGES - 1; ++p) {
        load_stage(sb_, p, Abase, Bbase, p, tid);
        cp_commit();
    }

    // Pre-swizzled ldmatrix base addresses (ks=0). In-loop k-step advance is a
    // pure XOR: un-swizzled column byte < 32 and kbyte in {0,32,64,96} touches
    // only bits 5-6, so swz(base + kbyte) == swz(base) ^ kbyte.
    uint32_t a_base[2], b_base[4];
#pragma unroll
    for (int mt = 0; mt < 2; ++mt) {
        int r = wm * 32 + mt * 16 + (lane & 15);
        int cbyte = (lane >> 4) * 16;
        a_base[mt] = swz((uint32_t)(r * 128 + cbyte));
    }
#pragma unroll
    for (int p = 0; p < 4; ++p) {
        int m = lane >> 3;
        int r = wn * 64 + p * 16 + ((m >> 1) * 8) + (lane & 7);
        int cbyte = (m & 1) * 16;
        b_base[p] = swz((uint32_t)(r * 128 + cbyte));
    }

    for (int i = 0; i < KTILES; ++i) {
        cp_wait<STAGES - 2>();
        __syncthreads();          // single barrier per iteration

        int pf = i + STAGES - 1;
        if (pf < KTILES) {
            load_stage(sb_, pf % STAGES, Abase, Bbase, pf, tid);
        }
        cp_commit();              // uniform group count even when empty

        uint32_t stA = sb_ + (i % STAGES) * STAGE_B;
        uint32_t stB = stA + A_STAGE;
#pragma unroll
        for (int ks = 0; ks < 4; ++ks) {
            uint32_t kx = (uint32_t)(ks * 32);
            uint32_t af[2][4];
#pragma unroll
            for (int mt = 0; mt < 2; ++mt)
                ldmatrix_x4(af[mt][0], af[mt][1], af[mt][2], af[mt][3],
                            stA + (a_base[mt] ^ kx));
            uint32_t bf[8][2];
#pragma unroll
            for (int p = 0; p < 4; ++p) {
                uint32_t r0, r1, r2, r3;
                ldmatrix_x4(r0, r1, r2, r3, stB + (b_base[p] ^ kx));
                bf[p*2+0][0] = r0; bf[p*2+0][1] = r1;
                bf[p*2+1][0] = r2; bf[p*2+1][1] = r3;
            }
#pragma unroll
            for (int mt = 0; mt < 2; ++mt)
#pragma unroll
                for (int nt = 0; nt < 8; ++nt)
                    mma_bf16(c[mt][nt][0], c[mt][nt][1], c[mt][nt][2], c[mt][nt][3],
                             af[mt][0], af[mt][1], af[mt][2], af[mt][3],
                             bf[nt][0], bf[nt][1]);
        }
    }

    // epilogue: direct global stores (float2 per reg pair)
    int g = lane >> 2, t4 = lane & 3;
    float* obase = out + ((size_t)b << 24)
                 + (size_t)(tm * BM + wm * 32) * DIM + tn * BN + wn * 64;
#pragma unroll
    for (int mt = 0; mt < 2; ++mt) {
#pragma unroll
        for (int nt = 0; nt < 8; ++nt) {
            int colb = nt * 8 + t4 * 2;
            float* p0 = obase + (size_t)(mt * 16 + g) * DIM + colb;
            *(float2*)p0 = make_float2(c[mt][nt][0], c[mt][nt][1]);
            float* p1 = obase + (size_t)(mt * 16 + g + 8) * DIM + colb;
            *(float2*)p1 = make_float2(c[mt][nt][2], c[mt][nt][3]);
        }
    }
}

// ---------------------------------------------------------------------------
extern "C" void kernel_launch(void* const* d_in, const int* in_sizes, int n_in,
                              void* d_out, int out_size) {
    const float* A = (const float*)d_in[0];
    const float* B = (const float*)d_in[1];
    float* out = (float*)d_out;

    quantA_kernel<<<(BATCH * DIM * KB) / 256, 256>>>(A);
    quantB_kernel<<<dim3(DIM / 256, KB, BATCH), 256>>>(B);

    cudaFuncSetAttribute(gemm_kernel, cudaFuncAttributeMaxDynamicSharedMemorySize, SMEM_TOTAL);
    gemm_kernel<<<dim3(DIM / BN, DIM / BM, BATCH), NTHREADS, SMEM_TOTAL>>>(out);
}